// round 12
// baseline (speedup 1.0000x reference)
#include <cuda_runtime.h>

// PinnWithGRU: B=2048 seqs, T=2048 steps, D=3, H=32.
// One warp per sequence, one hidden unit per lane, 2 warps/CTA.
// Hidden GEMV via packed f32x2 FFMA2 (even/odd k-split, 2-way chain split),
// weights pre-scaled by -log2e / -2log2e so activations are rcp(1+ex2(acc)).
// No syncwarp: convergent-warp STS->LDS is in-order through the LSU.
#define BB 2048
#define TT 2048
#define DD 3
#define HH 32

using ull = unsigned long long;

__device__ __forceinline__ ull ffma2(ull a, ull b, ull c) {
    ull d;
    asm("fma.rn.f32x2 %0, %1, %2, %3;" : "=l"(d) : "l"(a), "l"(b), "l"(c));
    return d;
}
__device__ __forceinline__ ull addf2(ull a, ull b) {
    ull d;
    asm("add.rn.f32x2 %0, %1, %2;" : "=l"(d) : "l"(a), "l"(b));
    return d;
}
__device__ __forceinline__ ull pack2(float lo, float hi) {
    ull r;
    asm("mov.b64 %0, {%1, %2};" : "=l"(r) : "f"(lo), "f"(hi));
    return r;
}
__device__ __forceinline__ void unpack2(ull v, float& lo, float& hi) {
    asm("mov.b64 {%0, %1}, %2;" : "=f"(lo), "=f"(hi) : "l"(v));
}
__device__ __forceinline__ float ex2f(float x) {
    float y; asm("ex2.approx.f32 %0, %1;" : "=f"(y) : "f"(x)); return y;
}
__device__ __forceinline__ float rcpf(float x) {
    float y; asm("rcp.approx.f32 %0, %1;" : "=f"(y) : "f"(x)); return y;
}

__global__ __launch_bounds__(64, 7)
void gru_scan_kernel(const float* __restrict__ inp,     // [B, T, 3]
                     const float* __restrict__ Wih,     // [96, 3]
                     const float* __restrict__ Whh,     // [96, 32]
                     const float* __restrict__ bias,    // [96]
                     const float* __restrict__ bias_n,  // [32]
                     float* __restrict__ out)           // [B, T]
{
    const int lane = threadIdx.x & 31;
    const int wid  = threadIdx.x >> 5;            // warp in CTA (0..1)
    const int b    = blockIdx.x * 2 + wid;
    if (b >= BB) return;

    __shared__ __align__(16) float hsh[2][HH];    // [warp][unit], single buffer

    const float L2E = 1.4426950408889634f;
    const float cRZ = -L2E;          // sigmoid gates: acc = -log2e * pre-act
    const float cA  = -2.0f * L2E;   // tanh gate:     acc = -2log2e * pre-act

    // --- W_hh rows for this lane, pre-scaled, packed (even k, odd k) ---
    ull wr2[16], wz2[16], wa2[16];
    const float4* whh4 = reinterpret_cast<const float4*>(Whh);
    #pragma unroll
    for (int k4 = 0; k4 < 8; k4++) {
        float4 v;
        v = whh4[(0 * HH + lane) * 8 + k4];
        wr2[2*k4]   = pack2(cRZ * v.x, cRZ * v.y);
        wr2[2*k4+1] = pack2(cRZ * v.z, cRZ * v.w);
        v = whh4[(1 * HH + lane) * 8 + k4];
        wz2[2*k4]   = pack2(cRZ * v.x, cRZ * v.y);
        wz2[2*k4+1] = pack2(cRZ * v.z, cRZ * v.w);
        v = whh4[(2 * HH + lane) * 8 + k4];
        wa2[2*k4]   = pack2(cA * v.x, cA * v.y);
        wa2[2*k4+1] = pack2(cA * v.z, cA * v.w);
    }

    // Input-gate weights + biases, pre-scaled the same way
    const float wir0 = cRZ * Wih[(0*HH + lane)*DD + 0];
    const float wir1 = cRZ * Wih[(0*HH + lane)*DD + 1];
    const float wir2 = cRZ * Wih[(0*HH + lane)*DD + 2];
    const float wiz0 = cRZ * Wih[(1*HH + lane)*DD + 0];
    const float wiz1 = cRZ * Wih[(1*HH + lane)*DD + 1];
    const float wiz2 = cRZ * Wih[(1*HH + lane)*DD + 2];
    const float wia0 = cA  * Wih[(2*HH + lane)*DD + 0];
    const float wia1 = cA  * Wih[(2*HH + lane)*DD + 1];
    const float wia2 = cA  * Wih[(2*HH + lane)*DD + 2];
    const float br = cRZ * bias[0*HH + lane];
    const float bz = cRZ * bias[1*HH + lane];
    const float ba = cA  * (bias[2*HH + lane] + bias_n[lane]);

    const float4* __restrict__ x4 = reinterpret_cast<const float4*>(inp + (size_t)b * TT * DD);
    float*        __restrict__ op = out + (size_t)b * TT;
    float* hbuf = hsh[wid];

    float h = 0.0f;

    // First group of 4 steps (12 floats = 3x float4)
    float4 xa = x4[0], xb = x4[1], xc = x4[2];

    //  pr sum = -L*(ir + W_r.h)        -> r = 1/(1+2^pr) = sigmoid(ir+hr)
    //  pz sum = -L*(iz + W_z.h)        -> z likewise
    //  arg    = -2L*(ia + ban + r*ha)  -> n = 2/(1+2^arg) - 1 = tanh(...)
    #define GRU_STEP(IR, IZ, IA, TIDX)                                          \
    {                                                                           \
        hbuf[lane] = h;                                                         \
        const ulonglong2* hb = reinterpret_cast<const ulonglong2*>(hbuf);       \
        ull pr0 = pack2((IR), 0.0f), pr1 = 0ull;                                \
        ull pz0 = pack2((IZ), 0.0f), pz1 = 0ull;                                \
        ull pa0 = 0ull,              pa1 = 0ull;                                \
        _Pragma("unroll")                                                       \
        for (int q = 0; q < 8; q++) {                                           \
            const ulonglong2 hv = hb[q];                                        \
            pr0 = ffma2(wr2[2*q],   hv.x, pr0);                                 \
            pr1 = ffma2(wr2[2*q+1], hv.y, pr1);                                 \
            pz0 = ffma2(wz2[2*q],   hv.x, pz0);                                 \
            pz1 = ffma2(wz2[2*q+1], hv.y, pz1);                                 \
            pa0 = ffma2(wa2[2*q],   hv.x, pa0);                                 \
            pa1 = ffma2(wa2[2*q+1], hv.y, pa1);                                 \
        }                                                                       \
        float rl, rh, zl, zh, al, ah;                                           \
        unpack2(addf2(pr0, pr1), rl, rh);                                       \
        unpack2(addf2(pz0, pz1), zl, zh);                                       \
        unpack2(addf2(pa0, pa1), al, ah);                                       \
        const float r  = rcpf(1.0f + ex2f(rl + rh));                            \
        const float z  = rcpf(1.0f + ex2f(zl + zh));                            \
        const float tn = rcpf(1.0f + ex2f(fmaf(r, al + ah, (IA))));             \
        const float n  = fmaf(2.0f, tn, -1.0f);                                 \
        h = fmaf(z, h - n, n);                                                  \
        if (lane == 0) op[TIDX] = h;                                            \
    }

    const int NG = TT / 4;
    for (int g = 0; g < NG; g++) {
        // Precompute all 4 steps' input gates (independent of h): filler work
        // for the recurrence's dependency bubbles.
        const float i0r = fmaf(wir2, xa.z, fmaf(wir1, xa.y, fmaf(wir0, xa.x, br)));
        const float i0z = fmaf(wiz2, xa.z, fmaf(wiz1, xa.y, fmaf(wiz0, xa.x, bz)));
        const float i0a = fmaf(wia2, xa.z, fmaf(wia1, xa.y, fmaf(wia0, xa.x, ba)));
        const float i1r = fmaf(wir2, xb.y, fmaf(wir1, xb.x, fmaf(wir0, xa.w, br)));
        const float i1z = fmaf(wiz2, xb.y, fmaf(wiz1, xb.x, fmaf(wiz0, xa.w, bz)));
        const float i1a = fmaf(wia2, xb.y, fmaf(wia1, xb.x, fmaf(wia0, xa.w, ba)));
        const float i2r = fmaf(wir2, xc.x, fmaf(wir1, xb.w, fmaf(wir0, xb.z, br)));
        const float i2z = fmaf(wiz2, xc.x, fmaf(wiz1, xb.w, fmaf(wiz0, xb.z, bz)));
        const float i2a = fmaf(wia2, xc.x, fmaf(wia1, xb.w, fmaf(wia0, xb.z, ba)));
        const float i3r = fmaf(wir2, xc.w, fmaf(wir1, xc.z, fmaf(wir0, xc.y, br)));
        const float i3z = fmaf(wiz2, xc.w, fmaf(wiz1, xc.z, fmaf(wiz0, xc.y, bz)));
        const float i3a = fmaf(wia2, xc.w, fmaf(wia1, xc.z, fmaf(wia0, xc.y, ba)));

        // x regs now dead: prefetch next group a full group (~4 steps) ahead.
        const int gn3 = ((g + 1 < NG) ? (g + 1) : g) * 3;
        xa = x4[gn3 + 0];
        xb = x4[gn3 + 1];
        xc = x4[gn3 + 2];

        const int t0 = g * 4;
        GRU_STEP(i0r, i0z, i0a, t0);
        GRU_STEP(i1r, i1z, i1a, t0 + 1);
        GRU_STEP(i2r, i2z, i2a, t0 + 2);
        GRU_STEP(i3r, i3z, i3a, t0 + 3);
    }
    #undef GRU_STEP
}

extern "C" void kernel_launch(void* const* d_in, const int* in_sizes, int n_in,
                              void* d_out, int out_size) {
    const float* inp    = (const float*)d_in[0];
    const float* wih    = (const float*)d_in[1];
    const float* whh    = (const float*)d_in[2];
    const float* bias   = (const float*)d_in[3];
    const float* bias_n = (const float*)d_in[4];
    float* out = (float*)d_out;

    gru_scan_kernel<<<BB / 2, 64>>>(inp, wih, whh, bias, bias_n, out);
}

// round 13
// speedup vs baseline: 1.2373x; 1.2373x over previous
#include <cuda_runtime.h>

// PinnWithGRU: B=2048 seqs, T=2048 steps, D=3, H=32.
// TWO sequences per warp (shared weight registers, 2 independent recurrence
// chains interleaved for ILP), one hidden unit per lane, 2 warps/CTA.
// Hidden GEMV via packed f32x2 FFMA2; weights pre-scaled by -log2e / -2log2e
// so activations are rcp(1+ex2(acc)). Same per-seq arithmetic as the 975us R7.
#define BB 2048
#define TT 2048
#define DD 3
#define HH 32

using ull = unsigned long long;

__device__ __forceinline__ ull ffma2(ull a, ull b, ull c) {
    ull d;
    asm("fma.rn.f32x2 %0, %1, %2, %3;" : "=l"(d) : "l"(a), "l"(b), "l"(c));
    return d;
}
__device__ __forceinline__ ull pack2(float lo, float hi) {
    ull r;
    asm("mov.b64 %0, {%1, %2};" : "=l"(r) : "f"(lo), "f"(hi));
    return r;
}
__device__ __forceinline__ void unpack2(ull v, float& lo, float& hi) {
    asm("mov.b64 {%0, %1}, %2;" : "=f"(lo), "=f"(hi) : "l"(v));
}
__device__ __forceinline__ float ex2f(float x) {
    float y; asm("ex2.approx.f32 %0, %1;" : "=f"(y) : "f"(x)); return y;
}
__device__ __forceinline__ float rcpf(float x) {
    float y; asm("rcp.approx.f32 %0, %1;" : "=f"(y) : "f"(x)); return y;
}

__global__ __launch_bounds__(64)
void gru_scan_kernel(const float* __restrict__ inp,     // [B, T, 3]
                     const float* __restrict__ Wih,     // [96, 3]
                     const float* __restrict__ Whh,     // [96, 32]
                     const float* __restrict__ bias,    // [96]
                     const float* __restrict__ bias_n,  // [32]
                     float* __restrict__ out)           // [B, T]
{
    const int lane = threadIdx.x & 31;
    const int wid  = threadIdx.x >> 5;                 // warp in CTA (0..1)
    const int w    = blockIdx.x * 2 + wid;             // global warp id (0..1023)
    const int bA   = 2 * w;                            // first sequence
    const int bB   = bA + 1;                           // second sequence

    __shared__ __align__(16) float hsh[2][2][HH];      // [warp][seq][unit]

    const float L2E = 1.4426950408889634f;
    const float cRZ = -L2E;          // sigmoid gates: acc = -log2e * pre-act
    const float cA  = -2.0f * L2E;   // tanh gate:     acc = -2log2e * pre-act

    // --- W_hh rows for this lane, pre-scaled, packed (even k, odd k) ---
    // Shared by both sequences: the big register cost is amortized 2x.
    ull wr2[16], wz2[16], wa2[16];
    const float4* whh4 = reinterpret_cast<const float4*>(Whh);
    #pragma unroll
    for (int k4 = 0; k4 < 8; k4++) {
        float4 v;
        v = whh4[(0 * HH + lane) * 8 + k4];
        wr2[2*k4]   = pack2(cRZ * v.x, cRZ * v.y);
        wr2[2*k4+1] = pack2(cRZ * v.z, cRZ * v.w);
        v = whh4[(1 * HH + lane) * 8 + k4];
        wz2[2*k4]   = pack2(cRZ * v.x, cRZ * v.y);
        wz2[2*k4+1] = pack2(cRZ * v.z, cRZ * v.w);
        v = whh4[(2 * HH + lane) * 8 + k4];
        wa2[2*k4]   = pack2(cA * v.x, cA * v.y);
        wa2[2*k4+1] = pack2(cA * v.z, cA * v.w);
    }

    // Input-gate weights + biases, pre-scaled the same way (shared)
    const float wir0 = cRZ * Wih[(0*HH + lane)*DD + 0];
    const float wir1 = cRZ * Wih[(0*HH + lane)*DD + 1];
    const float wir2 = cRZ * Wih[(0*HH + lane)*DD + 2];
    const float wiz0 = cRZ * Wih[(1*HH + lane)*DD + 0];
    const float wiz1 = cRZ * Wih[(1*HH + lane)*DD + 1];
    const float wiz2 = cRZ * Wih[(1*HH + lane)*DD + 2];
    const float wia0 = cA  * Wih[(2*HH + lane)*DD + 0];
    const float wia1 = cA  * Wih[(2*HH + lane)*DD + 1];
    const float wia2 = cA  * Wih[(2*HH + lane)*DD + 2];
    const float br = cRZ * bias[0*HH + lane];
    const float bz = cRZ * bias[1*HH + lane];
    const float ba = cA  * (bias[2*HH + lane] + bias_n[lane]);

    const float4* __restrict__ x4A = reinterpret_cast<const float4*>(inp + (size_t)bA * TT * DD);
    const float4* __restrict__ x4B = reinterpret_cast<const float4*>(inp + (size_t)bB * TT * DD);
    float*        __restrict__ opA = out + (size_t)bA * TT;
    float*        __restrict__ opB = out + (size_t)bB * TT;
    float* hbufA = hsh[wid][0];
    float* hbufB = hsh[wid][1];

    float hA = 0.0f, hB = 0.0f;

    // First group of 4 steps per seq (12 floats = 3x float4 each)
    float4 xaA = x4A[0], xbA = x4A[1], xcA = x4A[2];
    float4 xaB = x4B[0], xbB = x4B[1], xcB = x4B[2];

    // One fused step advancing BOTH sequences: two independent dependency
    // chains interleave to fill each other's SMEM/MUFU latency bubbles.
    //  pr = -L*(ir + W_r.h)        -> r = 1/(1+2^pr) = sigmoid(ir+hr)
    //  pz = -L*(iz + W_z.h)        -> z likewise
    //  arg= -2L*(ia + ban + r*ha)  -> n = 2/(1+2^arg) - 1 = tanh(...)
    #define GRU_STEP2(A0, A1, A2, B0, B1, B2, TIDX)                             \
    {                                                                           \
        const float irA = fmaf(wir2,(A2), fmaf(wir1,(A1), fmaf(wir0,(A0), br)));\
        const float izA = fmaf(wiz2,(A2), fmaf(wiz1,(A1), fmaf(wiz0,(A0), bz)));\
        const float iaA = fmaf(wia2,(A2), fmaf(wia1,(A1), fmaf(wia0,(A0), ba)));\
        const float irB = fmaf(wir2,(B2), fmaf(wir1,(B1), fmaf(wir0,(B0), br)));\
        const float izB = fmaf(wiz2,(B2), fmaf(wiz1,(B1), fmaf(wiz0,(B0), bz)));\
        const float iaB = fmaf(wia2,(B2), fmaf(wia1,(B1), fmaf(wia0,(B0), ba)));\
        hbufA[lane] = hA;                                                       \
        hbufB[lane] = hB;                                                       \
        __syncwarp();                                                           \
        const ulonglong2* hbA = reinterpret_cast<const ulonglong2*>(hbufA);     \
        const ulonglong2* hbB = reinterpret_cast<const ulonglong2*>(hbufB);     \
        ull prA = pack2(irA, 0.0f), pzA = pack2(izA, 0.0f), paA = 0ull;         \
        ull prB = pack2(irB, 0.0f), pzB = pack2(izB, 0.0f), paB = 0ull;         \
        _Pragma("unroll")                                                       \
        for (int q = 0; q < 8; q++) {                                           \
            const ulonglong2 hvA = hbA[q];                                      \
            prA = ffma2(wr2[2*q],   hvA.x, prA);                                \
            prA = ffma2(wr2[2*q+1], hvA.y, prA);                                \
            pzA = ffma2(wz2[2*q],   hvA.x, pzA);                                \
            pzA = ffma2(wz2[2*q+1], hvA.y, pzA);                                \
            paA = ffma2(wa2[2*q],   hvA.x, paA);                                \
            paA = ffma2(wa2[2*q+1], hvA.y, paA);                                \
            const ulonglong2 hvB = hbB[q];                                      \
            prB = ffma2(wr2[2*q],   hvB.x, prB);                                \
            prB = ffma2(wr2[2*q+1], hvB.y, prB);                                \
            pzB = ffma2(wz2[2*q],   hvB.x, pzB);                                \
            pzB = ffma2(wz2[2*q+1], hvB.y, pzB);                                \
            paB = ffma2(wa2[2*q],   hvB.x, paB);                                \
            paB = ffma2(wa2[2*q+1], hvB.y, paB);                                \
        }                                                                       \
        float rlA, rhA, zlA, zhA, alA, ahA;                                     \
        float rlB, rhB, zlB, zhB, alB, ahB;                                     \
        unpack2(prA, rlA, rhA);                                                 \
        unpack2(pzA, zlA, zhA);                                                 \
        unpack2(paA, alA, ahA);                                                 \
        unpack2(prB, rlB, rhB);                                                 \
        unpack2(pzB, zlB, zhB);                                                 \
        unpack2(paB, alB, ahB);                                                 \
        const float rA  = rcpf(1.0f + ex2f(rlA + rhA));                         \
        const float rB  = rcpf(1.0f + ex2f(rlB + rhB));                         \
        const float zA  = rcpf(1.0f + ex2f(zlA + zhA));                         \
        const float zB  = rcpf(1.0f + ex2f(zlB + zhB));                         \
        const float tnA = rcpf(1.0f + ex2f(fmaf(rA, alA + ahA, iaA)));          \
        const float tnB = rcpf(1.0f + ex2f(fmaf(rB, alB + ahB, iaB)));          \
        const float nA  = fmaf(2.0f, tnA, -1.0f);                               \
        const float nB  = fmaf(2.0f, tnB, -1.0f);                               \
        hA = fmaf(zA, hA - nA, nA);                                             \
        hB = fmaf(zB, hB - nB, nB);                                             \
        if (lane == 0) { opA[TIDX] = hA; opB[TIDX] = hB; }                      \
    }

    const int NG = TT / 4;
    for (int g = 0; g < NG; g++) {
        const int gn3 = ((g + 1 < NG) ? (g + 1) : g) * 3;  // next group (clamped)
        const int t0  = g * 4;

        GRU_STEP2(xaA.x, xaA.y, xaA.z,  xaB.x, xaB.y, xaB.z,  t0);
        GRU_STEP2(xaA.w, xbA.x, xbA.y,  xaB.w, xbB.x, xbB.y,  t0 + 1);
        xaA = x4A[gn3 + 0];               // reload right after last use
        xaB = x4B[gn3 + 0];
        GRU_STEP2(xbA.z, xbA.w, xcA.x,  xbB.z, xbB.w, xcB.x,  t0 + 2);
        xbA = x4A[gn3 + 1];
        xbB = x4B[gn3 + 1];
        GRU_STEP2(xcA.y, xcA.z, xcA.w,  xcB.y, xcB.z, xcB.w,  t0 + 3);
        xcA = x4A[gn3 + 2];
        xcB = x4B[gn3 + 2];
    }
    #undef GRU_STEP2
}

extern "C" void kernel_launch(void* const* d_in, const int* in_sizes, int n_in,
                              void* d_out, int out_size) {
    const float* inp    = (const float*)d_in[0];
    const float* wih    = (const float*)d_in[1];
    const float* whh    = (const float*)d_in[2];
    const float* bias   = (const float*)d_in[3];
    const float* bias_n = (const float*)d_in[4];
    float* out = (float*)d_out;

    // 1024 warps, 2 seqs each: 512 CTAs x 64 threads
    gru_scan_kernel<<<BB / 4, 64>>>(inp, wih, whh, bias, bias_n, out);
}